// round 8
// baseline (speedup 1.0000x reference)
#include <cuda_runtime.h>
#include <cstdint>

#define N_NODES 1024
#define F_IN    32
#define HID     64
#define OUTF    32

typedef unsigned long long u64;

// Scratch
__device__ float  g_A  [N_NODES * HID];
__device__ float2 g_Bt [(HID / 2) * N_NODES];   // Bt[hp][i]
__device__ float  g_W2T[HID * OUTF];            // W2^T [h][o]

// Constant copies
__constant__ float c_W1 [HID * 2 * F_IN];       // W1 [h][0..63]
__constant__ float c_W2T[HID * OUTF];           // W2^T [h][o]
__constant__ float c_b2 [OUTF];

// ---------------------------------------------------------------------------
// Prep: 256 blocks x 256 threads, 4 nodes/block, W1 from constant (no smem,
// no syncs). Block 0 additionally writes the W2 transpose.
// ---------------------------------------------------------------------------
__global__ __launch_bounds__(256) void prep_kernel(const float* __restrict__ Emb,
                                                   const float* __restrict__ W2) {
    const int tid = threadIdx.x;

    if (blockIdx.x == 0) {
        for (int idx = tid; idx < OUTF * HID; idx += 256) {
            int o = idx >> 6, h = idx & 63;
            g_W2T[h * OUTF + o] = W2[idx];
        }
    }

    const int node = blockIdx.x * 4 + (tid >> 6);
    const int h    = tid & 63;

    const float4* e4 = (const float4*)(Emb + node * F_IN);
    float a = 0.f, b = 0.f;
#pragma unroll
    for (int f4 = 0; f4 < 8; f4++) {
        float4 e  = __ldg(e4 + f4);
        float4 wa = *(const float4*)(c_W1 + h * 64 + 4 * f4);
        float4 wb = *(const float4*)(c_W1 + h * 64 + F_IN + 4 * f4);
        a = fmaf(e.x, wa.x, fmaf(e.y, wa.y, fmaf(e.z, wa.z, fmaf(e.w, wa.w, a))));
        b = fmaf(e.x, wb.x, fmaf(e.y, wb.y, fmaf(e.z, wb.z, fmaf(e.w, wb.w, b))));
    }
    g_A[node * HID + h] = a;
    ((float*)g_Bt)[(h >> 1) * (2 * N_NODES) + node * 2 + (h & 1)] = b;
}

// ---------------------------------------------------------------------------
__device__ __forceinline__ u64 pack2(float lo, float hi) {
    u64 r; asm("mov.b64 %0, {%1,%2};" : "=l"(r) : "f"(lo), "f"(hi)); return r;
}
__device__ __forceinline__ void unpack2(u64 v, float& lo, float& hi) {
    asm("mov.b64 {%0,%1}, %2;" : "=f"(lo), "=f"(hi) : "l"(v));
}
__device__ __forceinline__ void fma2(u64& acc, u64 a, u64 b) {
    asm("fma.rn.f32x2 %0, %1, %2, %0;" : "+l"(acc) : "l"(a), "l"(b));
}
__device__ __forceinline__ u64 fma2r(u64 a, u64 b, u64 c) {
    u64 d; asm("fma.rn.f32x2 %0, %1, %2, %3;" : "=l"(d) : "l"(a), "l"(b), "l"(c)); return d;
}
__device__ __forceinline__ u64 add2r(u64 a, u64 b) {
    u64 d; asm("add.rn.f32x2 %0, %1, %2;" : "=l"(d) : "l"(a), "l"(b)); return d;
}
__device__ __forceinline__ u64 mul2r(u64 a, u64 b) {
    u64 d; asm("mul.rn.f32x2 %0, %1, %2;" : "=l"(d) : "l"(a), "l"(b)); return d;
}
__device__ __forceinline__ float tanhf_a(float x) {
    float t; asm("tanh.approx.f32 %0, %1;" : "=f"(t) : "f"(x)); return t;
}

// ---------------------------------------------------------------------------
// Main: grid (N/64, N/8), block 256 = 8 warps. Lane owns pairs (i, j0+lane)
// and (i, j0+32+lane). W2^T split across ports: o=0..15 from constant (LDC),
// o=16..31 from shared (broadcast LDS.128). Accumulators preseeded with b2.
// ---------------------------------------------------------------------------
__global__ __launch_bounds__(256, 2) void phi_e_kernel(
    const float* __restrict__ Edges,
    const float* __restrict__ Coords,
    const float* __restrict__ b1,
    float* __restrict__ out)
{
    __shared__ u64        sB2u[HID / 2][64];           // packed Bt tile (16 KB)
    __shared__ ulonglong2 sCAB[8][HID / 2];            // (packed A, packed b1) per warp (4 KB)
    __shared__ __align__(16) float sW2s[HID * 36];     // shared W2^T copy (9 KB)
    __shared__ float      sOut[8][32][17];             // epilogue staging (17.4 KB)

    const int tid  = threadIdx.x;
    const int warp = tid >> 5;
    const int lane = tid & 31;
    const int i0 = blockIdx.y * 8;
    const int j0 = blockIdx.x * 64;
    const int i  = i0 + warp;

    for (int e = tid; e < (HID / 2) * 64; e += 256) {
        int hp = e >> 6, jj = e & 63;
        float2 v = g_Bt[hp * N_NODES + j0 + jj];
        sB2u[hp][jj] = pack2(v.x, v.y);
    }
    for (int idx = tid; idx < HID * OUTF; idx += 256) {
        int h = idx >> 5, o = idx & 31;
        sW2s[h * 36 + o] = g_W2T[idx];
    }
    {
        float2 a2 = ((const float2*)g_A)[i * (HID / 2) + lane];
        float2 bb = ((const float2*)b1)[lane];
        ulonglong2 cb;
        cb.x = pack2(a2.x, a2.y);
        cb.y = pack2(bb.x, bb.y);
        sCAB[warp][lane] = cb;
    }

    float wA, wB;
    {
        float cx = Coords[i * 3 + 0], cy = Coords[i * 3 + 1], cz = Coords[i * 3 + 2];
        int jA = j0 + lane, jB = j0 + 32 + lane;
        float dxA = cx - Coords[jA * 3 + 0], dyA = cy - Coords[jA * 3 + 1], dzA = cz - Coords[jA * 3 + 2];
        float dxB = cx - Coords[jB * 3 + 0], dyB = cy - Coords[jB * 3 + 1], dzB = cz - Coords[jB * 3 + 2];
        float sqA = fmaf(dxA, dxA, fmaf(dyA, dyA, dzA * dzA));
        float sqB = fmaf(dxB, dxB, fmaf(dyB, dyB, dzB * dzB));
        float dA = sqA > 0.f ? __fsqrt_rn(sqA) : 0.f;
        float dB = sqB > 0.f ? __fsqrt_rn(sqB) : 0.f;
        wA = Edges[i * N_NODES + jA] * dA;
        wB = Edges[i * N_NODES + jB] * dB;
    }
    __syncthreads();

    const u64 wpA   = pack2(wA, wA);
    const u64 wpB   = pack2(wB, wB);
    const u64 halfp = pack2(0.5f, 0.5f);

    u64 accA[16], accB[16];
#pragma unroll
    for (int p = 0; p < 16; p++) {
        accA[p] = pack2(c_b2[2 * p], c_b2[2 * p + 1]);
        accB[p] = accA[p];
    }

#pragma unroll 4
    for (int hp = 0; hp < HID / 2; hp++) {
        ulonglong2 cb = sCAB[warp][hp];                // broadcast LDS.128
        u64 bA = sB2u[hp][lane];                       // LDS.64
        u64 bB = sB2u[hp][32 + lane];

        u64 preA = fma2r(wpA, add2r(cb.x, bA), cb.y);
        u64 preB = fma2r(wpB, add2r(cb.x, bB), cb.y);

        u64 hxA = mul2r(preA, halfp);
        u64 hxB = mul2r(preB, halfp);
        float hA0x, hA1x, hB0x, hB1x;
        unpack2(hxA, hA0x, hA1x);
        unpack2(hxB, hB0x, hB1x);
        float hA0 = fmaf(hA0x, tanhf_a(hA0x), hA0x);
        float hA1 = fmaf(hA1x, tanhf_a(hA1x), hA1x);
        float hB0 = fmaf(hB0x, tanhf_a(hB0x), hB0x);
        float hB1 = fmaf(hB1x, tanhf_a(hB1x), hB1x);

        u64 pA0 = pack2(hA0, hA0), pA1 = pack2(hA1, hA1);
        u64 pB0 = pack2(hB0, hB0), pB1 = pack2(hB1, hB1);

        const ulonglong2* cr0 = (const ulonglong2*)(c_W2T + (2 * hp)     * OUTF);
        const ulonglong2* cr1 = (const ulonglong2*)(c_W2T + (2 * hp + 1) * OUTF);
        const ulonglong2* sr0 = (const ulonglong2*)(sW2s + (2 * hp)     * 36);
        const ulonglong2* sr1 = (const ulonglong2*)(sW2s + (2 * hp + 1) * 36);

#pragma unroll
        for (int q = 0; q < 4; q++) {                  // o = 0..15 via constant port
            ulonglong2 w0 = cr0[q];
            ulonglong2 w1 = cr1[q];
            fma2(accA[2 * q],     pA0, w0.x);
            fma2(accA[2 * q + 1], pA0, w0.y);
            fma2(accA[2 * q],     pA1, w1.x);
            fma2(accA[2 * q + 1], pA1, w1.y);
            fma2(accB[2 * q],     pB0, w0.x);
            fma2(accB[2 * q + 1], pB0, w0.y);
            fma2(accB[2 * q],     pB1, w1.x);
            fma2(accB[2 * q + 1], pB1, w1.y);
        }
#pragma unroll
        for (int q = 4; q < 8; q++) {                  // o = 16..31 via shared port
            ulonglong2 w0 = sr0[q];
            ulonglong2 w1 = sr1[q];
            fma2(accA[2 * q],     pA0, w0.x);
            fma2(accA[2 * q + 1], pA0, w0.y);
            fma2(accA[2 * q],     pA1, w1.x);
            fma2(accA[2 * q + 1], pA1, w1.y);
            fma2(accB[2 * q],     pB0, w0.x);
            fma2(accB[2 * q + 1], pB0, w0.y);
            fma2(accB[2 * q],     pB1, w1.x);
            fma2(accB[2 * q + 1], pB1, w1.y);
        }
    }

    // ---- epilogue: swish + coalesced store via padded smem transpose ----
    const int t   = lane & 15;
    const int jj2 = lane >> 4;
#pragma unroll
    for (int s = 0; s < 2; s++) {
        u64* acc = s ? accB : accA;
        float* obase = out + ((size_t)i * N_NODES + j0 + (s ? 32 : 0)) * OUTF;

        float vals[32];
#pragma unroll
        for (int p = 0; p < 16; p++) {
            u64 hx2 = mul2r(acc[p], halfp);
            float h0, h1;
            unpack2(hx2, h0, h1);
            vals[2 * p]     = fmaf(h0, tanhf_a(h0), h0);
            vals[2 * p + 1] = fmaf(h1, tanhf_a(h1), h1);
        }

#pragma unroll
        for (int r = 0; r < 2; r++) {
#pragma unroll
            for (int k = 0; k < 16; k++) sOut[warp][lane][k] = vals[16 * r + k];
            __syncwarp();
#pragma unroll
            for (int c = 0; c < 16; c++) {
                int jj = 2 * c + jj2;
                obase[jj * OUTF + 16 * r + t] = sOut[warp][jj][t];
            }
            __syncwarp();
        }
    }
}

// ---------------------------------------------------------------------------
extern "C" void kernel_launch(void* const* d_in, const int* in_sizes, int n_in,
                              void* d_out, int out_size) {
    const float* Edges  = (const float*)d_in[0];
    const float* Coords = (const float*)d_in[1];
    const float* Emb    = (const float*)d_in[2];
    const float* W1     = (const float*)d_in[3];
    const float* b1     = (const float*)d_in[4];
    const float* W2     = (const float*)d_in[5];
    const float* b2     = (const float*)d_in[6];
    float* out = (float*)d_out;

    // Constant uploads available before prep / main (D2D memcpy nodes).
    cudaMemcpyToSymbolAsync(c_W1, W1, HID * 2 * F_IN * sizeof(float), 0,
                            cudaMemcpyDeviceToDevice);
    cudaMemcpyToSymbolAsync(c_b2, b2, OUTF * sizeof(float), 0,
                            cudaMemcpyDeviceToDevice);

    prep_kernel<<<256, 256>>>(Emb, W2);   // also writes g_W2T (block 0)

    void* w2t_dev = nullptr;
    cudaGetSymbolAddress(&w2t_dev, g_W2T);
    cudaMemcpyToSymbolAsync(c_W2T, w2t_dev, HID * OUTF * sizeof(float), 0,
                            cudaMemcpyDeviceToDevice);

    dim3 grid(N_NODES / 64, N_NODES / 8);
    phi_e_kernel<<<grid, 256>>>(Edges, Coords, b1, out);
}

// round 9
// speedup vs baseline: 1.8355x; 1.8355x over previous
#include <cuda_runtime.h>
#include <cstdint>

#define N_NODES 1024
#define F_IN    32
#define HID     64
#define OUTF    32

typedef unsigned long long u64;

// Scratch
__device__ float  g_A  [N_NODES * HID];
__device__ float2 g_Bt [(HID / 2) * N_NODES];   // Bt[hp][i]
__device__ float  g_W2T[HID * OUTF];            // W2^T [h][o]

// Constant copies (uniform broadcast operands -> constant port)
__constant__ float c_W2T[HID * OUTF];
__constant__ float c_b2 [OUTF];

// ---------------------------------------------------------------------------
// Prep: 128 blocks x 256 threads, 8 nodes/block. W1 staged in padded smem
// (vectorized loads). Block 0 also writes the W2 transpose into g_W2T.
// ---------------------------------------------------------------------------
__global__ __launch_bounds__(256) void prep_kernel(const float* __restrict__ Emb,
                                                   const float* __restrict__ W1,
                                                   const float* __restrict__ W2) {
    __shared__ float sW1[HID * 65];      // rows padded to 65 -> conflict-free reads
    __shared__ float sE[8 * F_IN];
    const int tid = threadIdx.x;
    const int i0  = blockIdx.x * 8;

    if (blockIdx.x == 0) {
        for (int idx = tid; idx < OUTF * HID; idx += 256) {
            int o = idx >> 6, h = idx & 63;
            g_W2T[h * OUTF + o] = W2[idx];     // coalesced read, strided write
        }
    }

    // Stage W1: 1024 float4 loads across 256 threads (4 rounds).
    {
        const float4* w4 = (const float4*)W1;
        for (int v = tid; v < HID * 2 * F_IN / 4; v += 256) {
            float4 w = __ldg(w4 + v);
            int r = v >> 4, c = (v & 15) * 4;
            float* dst = &sW1[r * 65 + c];
            dst[0] = w.x; dst[1] = w.y; dst[2] = w.z; dst[3] = w.w;
        }
    }
    // Stage 8 Emb rows (64 float4s).
    if (tid < 64) {
        float4 e = __ldg((const float4*)(Emb + i0 * F_IN) + tid);
        float* dst = &sE[tid * 4];
        dst[0] = e.x; dst[1] = e.y; dst[2] = e.z; dst[3] = e.w;
    }
    __syncthreads();

    const int h  = tid & 63;
    const int g  = tid >> 6;            // 0..3
#pragma unroll
    for (int k = 0; k < 2; k++) {
        const int n = g * 2 + k;        // 0..7
        const float* e = &sE[n * F_IN];
        float a = 0.f, b = 0.f;
#pragma unroll
        for (int f = 0; f < F_IN; f++) {
            float ev = e[f];
            a = fmaf(ev, sW1[h * 65 + f], a);
            b = fmaf(ev, sW1[h * 65 + F_IN + f], b);
        }
        const int i = i0 + n;
        g_A[i * HID + h] = a;
        ((float*)g_Bt)[(h >> 1) * (2 * N_NODES) + i * 2 + (h & 1)] = b;
    }
}

// ---------------------------------------------------------------------------
__device__ __forceinline__ u64 pack2(float lo, float hi) {
    u64 r; asm("mov.b64 %0, {%1,%2};" : "=l"(r) : "f"(lo), "f"(hi)); return r;
}
__device__ __forceinline__ void unpack2(u64 v, float& lo, float& hi) {
    asm("mov.b64 {%0,%1}, %2;" : "=f"(lo), "=f"(hi) : "l"(v));
}
__device__ __forceinline__ void fma2(u64& acc, u64 a, u64 b) {
    asm("fma.rn.f32x2 %0, %1, %2, %0;" : "+l"(acc) : "l"(a), "l"(b));
}
__device__ __forceinline__ u64 fma2r(u64 a, u64 b, u64 c) {
    u64 d; asm("fma.rn.f32x2 %0, %1, %2, %3;" : "=l"(d) : "l"(a), "l"(b), "l"(c)); return d;
}
__device__ __forceinline__ u64 add2r(u64 a, u64 b) {
    u64 d; asm("add.rn.f32x2 %0, %1, %2;" : "=l"(d) : "l"(a), "l"(b)); return d;
}
__device__ __forceinline__ u64 mul2r(u64 a, u64 b) {
    u64 d; asm("mul.rn.f32x2 %0, %1, %2;" : "=l"(d) : "l"(a), "l"(b)); return d;
}
__device__ __forceinline__ float tanhf_a(float x) {
    float t; asm("tanh.approx.f32 %0, %1;" : "=f"(t) : "f"(x)); return t;
}

// ---------------------------------------------------------------------------
// Main (= proven R6 structure): grid (N/64, N/8), block 256 = 8 warps. Lane
// owns pairs (i, j0+lane) and (i, j0+32+lane). Phase A packed f32x2; all of
// W2^T from the constant port; accumulators preseeded with b2; coalesced
// store via padded smem transpose (+ streaming hint).
// ---------------------------------------------------------------------------
__global__ __launch_bounds__(256, 2) void phi_e_kernel(
    const float* __restrict__ Edges,
    const float* __restrict__ Coords,
    const float* __restrict__ b1,
    float* __restrict__ out)
{
    __shared__ u64        sB2u[HID / 2][64];           // packed Bt tile (16 KB)
    __shared__ ulonglong2 sCAB[8][HID / 2];            // (packed A, packed b1) (4 KB)
    __shared__ float      sOut[8][32][17];             // epilogue staging (17.4 KB)

    const int tid  = threadIdx.x;
    const int warp = tid >> 5;
    const int lane = tid & 31;
    const int i0 = blockIdx.y * 8;
    const int j0 = blockIdx.x * 64;
    const int i  = i0 + warp;

    for (int e = tid; e < (HID / 2) * 64; e += 256) {
        int hp = e >> 6, jj = e & 63;
        float2 v = g_Bt[hp * N_NODES + j0 + jj];
        sB2u[hp][jj] = pack2(v.x, v.y);
    }
    {
        float2 a2 = ((const float2*)g_A)[i * (HID / 2) + lane];
        float2 bb = ((const float2*)b1)[lane];
        ulonglong2 cb;
        cb.x = pack2(a2.x, a2.y);
        cb.y = pack2(bb.x, bb.y);
        sCAB[warp][lane] = cb;
    }

    float wA, wB;
    {
        float cx = Coords[i * 3 + 0], cy = Coords[i * 3 + 1], cz = Coords[i * 3 + 2];
        int jA = j0 + lane, jB = j0 + 32 + lane;
        float dxA = cx - Coords[jA * 3 + 0], dyA = cy - Coords[jA * 3 + 1], dzA = cz - Coords[jA * 3 + 2];
        float dxB = cx - Coords[jB * 3 + 0], dyB = cy - Coords[jB * 3 + 1], dzB = cz - Coords[jB * 3 + 2];
        float sqA = fmaf(dxA, dxA, fmaf(dyA, dyA, dzA * dzA));
        float sqB = fmaf(dxB, dxB, fmaf(dyB, dyB, dzB * dzB));
        float dA = sqA > 0.f ? __fsqrt_rn(sqA) : 0.f;
        float dB = sqB > 0.f ? __fsqrt_rn(sqB) : 0.f;
        wA = Edges[i * N_NODES + jA] * dA;
        wB = Edges[i * N_NODES + jB] * dB;
    }
    __syncthreads();

    const u64 wpA   = pack2(wA, wA);
    const u64 wpB   = pack2(wB, wB);
    const u64 halfp = pack2(0.5f, 0.5f);

    u64 accA[16], accB[16];
#pragma unroll
    for (int p = 0; p < 16; p++) {
        accA[p] = pack2(c_b2[2 * p], c_b2[2 * p + 1]);
        accB[p] = accA[p];
    }

#pragma unroll 4
    for (int hp = 0; hp < HID / 2; hp++) {
        ulonglong2 cb = sCAB[warp][hp];                // broadcast LDS.128
        u64 bA = sB2u[hp][lane];                       // LDS.64
        u64 bB = sB2u[hp][32 + lane];

        u64 preA = fma2r(wpA, add2r(cb.x, bA), cb.y);
        u64 preB = fma2r(wpB, add2r(cb.x, bB), cb.y);

        u64 hxA = mul2r(preA, halfp);
        u64 hxB = mul2r(preB, halfp);
        float hA0x, hA1x, hB0x, hB1x;
        unpack2(hxA, hA0x, hA1x);
        unpack2(hxB, hB0x, hB1x);
        float hA0 = fmaf(hA0x, tanhf_a(hA0x), hA0x);
        float hA1 = fmaf(hA1x, tanhf_a(hA1x), hA1x);
        float hB0 = fmaf(hB0x, tanhf_a(hB0x), hB0x);
        float hB1 = fmaf(hB1x, tanhf_a(hB1x), hB1x);

        u64 pA0 = pack2(hA0, hA0), pA1 = pack2(hA1, hA1);
        u64 pB0 = pack2(hB0, hB0), pB1 = pack2(hB1, hB1);

        const ulonglong2* r0 = (const ulonglong2*)(c_W2T + (2 * hp)     * OUTF);
        const ulonglong2* r1 = (const ulonglong2*)(c_W2T + (2 * hp + 1) * OUTF);
#pragma unroll
        for (int q = 0; q < 8; q++) {
            ulonglong2 w0 = r0[q];                     // uniform LDC.128
            ulonglong2 w1 = r1[q];
            fma2(accA[2 * q],     pA0, w0.x);
            fma2(accA[2 * q + 1], pA0, w0.y);
            fma2(accA[2 * q],     pA1, w1.x);
            fma2(accA[2 * q + 1], pA1, w1.y);
            fma2(accB[2 * q],     pB0, w0.x);
            fma2(accB[2 * q + 1], pB0, w0.y);
            fma2(accB[2 * q],     pB1, w1.x);
            fma2(accB[2 * q + 1], pB1, w1.y);
        }
    }

    // ---- epilogue: swish + coalesced streaming store via smem transpose ----
    const int t   = lane & 15;
    const int jj2 = lane >> 4;
#pragma unroll
    for (int s = 0; s < 2; s++) {
        u64* acc = s ? accB : accA;
        float* obase = out + ((size_t)i * N_NODES + j0 + (s ? 32 : 0)) * OUTF;

        float vals[32];
#pragma unroll
        for (int p = 0; p < 16; p++) {
            u64 hx2 = mul2r(acc[p], halfp);
            float h0, h1;
            unpack2(hx2, h0, h1);
            vals[2 * p]     = fmaf(h0, tanhf_a(h0), h0);
            vals[2 * p + 1] = fmaf(h1, tanhf_a(h1), h1);
        }

#pragma unroll
        for (int r = 0; r < 2; r++) {
#pragma unroll
            for (int k = 0; k < 16; k++) sOut[warp][lane][k] = vals[16 * r + k];
            __syncwarp();
#pragma unroll
            for (int c = 0; c < 16; c++) {
                int jj = 2 * c + jj2;
                __stcs(&obase[jj * OUTF + 16 * r + t], sOut[warp][jj][t]);
            }
            __syncwarp();
        }
    }
}

// ---------------------------------------------------------------------------
extern "C" void kernel_launch(void* const* d_in, const int* in_sizes, int n_in,
                              void* d_out, int out_size) {
    const float* Edges  = (const float*)d_in[0];
    const float* Coords = (const float*)d_in[1];
    const float* Emb    = (const float*)d_in[2];
    const float* W1     = (const float*)d_in[3];
    const float* b1     = (const float*)d_in[4];
    const float* W2     = (const float*)d_in[5];
    const float* b2     = (const float*)d_in[6];
    float* out = (float*)d_out;

    cudaMemcpyToSymbolAsync(c_b2, b2, OUTF * sizeof(float), 0,
                            cudaMemcpyDeviceToDevice);

    prep_kernel<<<128, 256>>>(Emb, W1, W2);   // also writes g_W2T (block 0)

    void* w2t_dev = nullptr;
    cudaGetSymbolAddress(&w2t_dev, g_W2T);
    cudaMemcpyToSymbolAsync(c_W2T, w2t_dev, HID * OUTF * sizeof(float), 0,
                            cudaMemcpyDeviceToDevice);

    dim3 grid(N_NODES / 64, N_NODES / 8);
    phi_e_kernel<<<grid, 256>>>(Edges, Coords, b1, out);
}

// round 11
// speedup vs baseline: 1.9887x; 1.0835x over previous
#include <cuda_runtime.h>
#include <cstdint>

#define N_NODES 1024
#define F_IN    32
#define HID     64
#define OUTF    32

typedef unsigned long long u64;

// Scratch
__device__ float g_A [N_NODES * HID];
__device__ float g_Bq[16 * N_NODES * 4];   // quad-packed: [hq][node][4 floats]
__device__ float g_W2T[HID * OUTF];        // W2^T [h][o]

// Constant copies (uniform broadcast operands -> constant port)
__constant__ float c_W2T[HID * OUTF];
__constant__ float c_b2 [OUTF];

// ---------------------------------------------------------------------------
// Prep: 128 blocks x 256 threads, 8 nodes/block. W1 staged in padded smem.
// Block 0 also writes the W2 transpose into g_W2T.
// ---------------------------------------------------------------------------
__global__ __launch_bounds__(256) void prep_kernel(const float* __restrict__ Emb,
                                                   const float* __restrict__ W1,
                                                   const float* __restrict__ W2) {
    __shared__ float sW1[HID * 65];
    __shared__ float sE[8 * F_IN];
    const int tid = threadIdx.x;
    const int i0  = blockIdx.x * 8;

    if (blockIdx.x == 0) {
        for (int idx = tid; idx < OUTF * HID; idx += 256) {
            int o = idx >> 6, h = idx & 63;
            g_W2T[h * OUTF + o] = W2[idx];
        }
    }

    {
        const float4* w4 = (const float4*)W1;
        for (int v = tid; v < HID * 2 * F_IN / 4; v += 256) {
            float4 w = __ldg(w4 + v);
            int r = v >> 4, c = (v & 15) * 4;
            float* dst = &sW1[r * 65 + c];
            dst[0] = w.x; dst[1] = w.y; dst[2] = w.z; dst[3] = w.w;
        }
    }
    if (tid < 64) {
        float4 e = __ldg((const float4*)(Emb + i0 * F_IN) + tid);
        float* dst = &sE[tid * 4];
        dst[0] = e.x; dst[1] = e.y; dst[2] = e.z; dst[3] = e.w;
    }
    __syncthreads();

    const int h = tid & 63;
    const int g = tid >> 6;
#pragma unroll
    for (int k = 0; k < 2; k++) {
        const int n = g * 2 + k;
        const float* e = &sE[n * F_IN];
        float a = 0.f, b = 0.f;
#pragma unroll
        for (int f = 0; f < F_IN; f++) {
            float ev = e[f];
            a = fmaf(ev, sW1[h * 65 + f], a);
            b = fmaf(ev, sW1[h * 65 + F_IN + f], b);
        }
        const int i = i0 + n;
        g_A[i * HID + h] = a;
        g_Bq[(h >> 2) * (N_NODES * 4) + i * 4 + (h & 3)] = b;
    }
}

// ---------------------------------------------------------------------------
__device__ __forceinline__ u64 pack2(float lo, float hi) {
    u64 r; asm("mov.b64 %0, {%1,%2};" : "=l"(r) : "f"(lo), "f"(hi)); return r;
}
__device__ __forceinline__ void unpack2(u64 v, float& lo, float& hi) {
    asm("mov.b64 {%0,%1}, %2;" : "=f"(lo), "=f"(hi) : "l"(v));
}
__device__ __forceinline__ void fma2(u64& acc, u64 a, u64 b) {
    asm("fma.rn.f32x2 %0, %1, %2, %0;" : "+l"(acc) : "l"(a), "l"(b));
}
__device__ __forceinline__ u64 fma2r(u64 a, u64 b, u64 c) {
    u64 d; asm("fma.rn.f32x2 %0, %1, %2, %3;" : "=l"(d) : "l"(a), "l"(b), "l"(c)); return d;
}
__device__ __forceinline__ u64 add2r(u64 a, u64 b) {
    u64 d; asm("add.rn.f32x2 %0, %1, %2;" : "=l"(d) : "l"(a), "l"(b)); return d;
}
__device__ __forceinline__ u64 mul2r(u64 a, u64 b) {
    u64 d; asm("mul.rn.f32x2 %0, %1, %2;" : "=l"(d) : "l"(a), "l"(b)); return d;
}
__device__ __forceinline__ float tanhf_a(float x) {
    float t; asm("tanh.approx.f32 %0, %1;" : "=f"(t) : "f"(x)); return t;
}
// h = hx + hx*tanh(hx) where hx = pre1/2  (swish with the 0.5 pre-folded)
__device__ __forceinline__ float swish_from_half(float hx) {
    return fmaf(hx, tanhf_a(hx), hx);
}

// ---------------------------------------------------------------------------
// Dynamic smem layout (bytes)
// ---------------------------------------------------------------------------
#define SM_BQ   0        // 16 hq x 64 j x 16B = 16384
#define SM_AQ   16384    // 8 warps x 16 hq x 16B = 2048
#define SM_B1Q  18432    // 16 x 16B = 256 (b1/2, quad-packed)
#define SM_OUT  18688    // 8 warps x 32 lanes x 36 floats = 36864
#define SMEM_TOTAL 55552

// ---------------------------------------------------------------------------
// Main: grid (N/64, N/8), block 256 = 8 warps. Lane owns pairs (i, j0+lane)
// and (i, j0+32+lane). Phase A packed f32x2 with 0.5 folded into w and b1;
// B tile quad-packed for LDS.128; W2^T from constant port; b2-preseeded accs;
// epilogue: STS.128 stage + LDS.64/STG.64 transpose (2 lines per store).
// ---------------------------------------------------------------------------
__global__ __launch_bounds__(256, 2) void phi_e_kernel(
    const float* __restrict__ Edges,
    const float* __restrict__ Coords,
    const float* __restrict__ b1,
    float* __restrict__ out)
{
    extern __shared__ __align__(16) char smem[];
    ulonglong2 (*sBq)[64] = (ulonglong2(*)[64])(smem + SM_BQ);
    ulonglong2 (*sAq)[16] = (ulonglong2(*)[16])(smem + SM_AQ);
    ulonglong2* sB1q      = (ulonglong2*)(smem + SM_B1Q);
    float*      sOutBase  = (float*)(smem + SM_OUT);

    const int tid  = threadIdx.x;
    const int warp = tid >> 5;
    const int lane = tid & 31;
    const int i0 = blockIdx.y * 8;
    const int j0 = blockIdx.x * 64;
    const int i  = i0 + warp;

    // Stage quad-packed B tile (coalesced 16B loads).
    {
        const ulonglong2* src = (const ulonglong2*)g_Bq;
        for (int e = tid; e < 16 * 64; e += 256) {
            int hq = e >> 6, jj = e & 63;
            sBq[hq][jj] = src[hq * N_NODES + j0 + jj];
        }
    }
    // Per-warp A quads.
    if (lane < 16)
        ((float4*)&sAq[warp][0])[lane] = ((const float4*)(g_A + i * HID))[lane];
    // b1/2 quads.
    if (tid < 16) {
        float4 v = ((const float4*)b1)[tid];
        v.x *= 0.5f; v.y *= 0.5f; v.z *= 0.5f; v.w *= 0.5f;
        ((float4*)sB1q)[tid] = v;
    }

    float wA, wB;
    {
        float cx = Coords[i * 3 + 0], cy = Coords[i * 3 + 1], cz = Coords[i * 3 + 2];
        int jA = j0 + lane, jB = j0 + 32 + lane;
        float dxA = cx - Coords[jA * 3 + 0], dyA = cy - Coords[jA * 3 + 1], dzA = cz - Coords[jA * 3 + 2];
        float dxB = cx - Coords[jB * 3 + 0], dyB = cy - Coords[jB * 3 + 1], dzB = cz - Coords[jB * 3 + 2];
        float sqA = fmaf(dxA, dxA, fmaf(dyA, dyA, dzA * dzA));
        float sqB = fmaf(dxB, dxB, fmaf(dyB, dyB, dzB * dzB));
        float dA = sqA > 0.f ? __fsqrt_rn(sqA) : 0.f;
        float dB = sqB > 0.f ? __fsqrt_rn(sqB) : 0.f;
        wA = Edges[i * N_NODES + jA] * dA;
        wB = Edges[i * N_NODES + jB] * dB;
    }
    __syncthreads();

    const u64 wAh = pack2(0.5f * wA, 0.5f * wA);   // w/2 packed
    const u64 wBh = pack2(0.5f * wB, 0.5f * wB);
    const u64 halfp = pack2(0.5f, 0.5f);

    u64 accA[16], accB[16];
#pragma unroll
    for (int p = 0; p < 16; p++) {
        accA[p] = pack2(c_b2[2 * p], c_b2[2 * p + 1]);
        accB[p] = accA[p];
    }

#pragma unroll 4
    for (int hq = 0; hq < 16; hq++) {
        ulonglong2 aq  = sAq[warp][hq];            // broadcast LDS.128
        ulonglong2 b1q = sB1q[hq];                 // broadcast LDS.128
        ulonglong2 bA  = sBq[hq][lane];            // LDS.128 conflict-free
        ulonglong2 bB  = sBq[hq][32 + lane];

        // hx = (w*(A+B) + b1)/2 directly (0.5 folded into w and b1)
        u64 xA0 = fma2r(wAh, add2r(aq.x, bA.x), b1q.x);
        u64 xA1 = fma2r(wAh, add2r(aq.y, bA.y), b1q.y);
        u64 xB0 = fma2r(wBh, add2r(aq.x, bB.x), b1q.x);
        u64 xB1 = fma2r(wBh, add2r(aq.y, bB.y), b1q.y);

        float a0, a1, a2, a3, c0, c1, c2, c3;
        unpack2(xA0, a0, a1); unpack2(xA1, a2, a3);
        unpack2(xB0, c0, c1); unpack2(xB1, c2, c3);
        a0 = swish_from_half(a0); a1 = swish_from_half(a1);
        a2 = swish_from_half(a2); a3 = swish_from_half(a3);
        c0 = swish_from_half(c0); c1 = swish_from_half(c1);
        c2 = swish_from_half(c2); c3 = swish_from_half(c3);

        u64 pA0 = pack2(a0, a0), pA1 = pack2(a1, a1);
        u64 pA2 = pack2(a2, a2), pA3 = pack2(a3, a3);
        u64 pB0 = pack2(c0, c0), pB1 = pack2(c1, c1);
        u64 pB2 = pack2(c2, c2), pB3 = pack2(c3, c3);

        const ulonglong2* r0 = (const ulonglong2*)(c_W2T + (4 * hq + 0) * OUTF);
        const ulonglong2* r1 = (const ulonglong2*)(c_W2T + (4 * hq + 1) * OUTF);
        const ulonglong2* r2 = (const ulonglong2*)(c_W2T + (4 * hq + 2) * OUTF);
        const ulonglong2* r3 = (const ulonglong2*)(c_W2T + (4 * hq + 3) * OUTF);
#pragma unroll
        for (int q = 0; q < 8; q++) {
            ulonglong2 w0 = r0[q], w1 = r1[q], w2 = r2[q], w3 = r3[q];
            fma2(accA[2 * q],     pA0, w0.x); fma2(accA[2 * q + 1], pA0, w0.y);
            fma2(accA[2 * q],     pA1, w1.x); fma2(accA[2 * q + 1], pA1, w1.y);
            fma2(accA[2 * q],     pA2, w2.x); fma2(accA[2 * q + 1], pA2, w2.y);
            fma2(accA[2 * q],     pA3, w3.x); fma2(accA[2 * q + 1], pA3, w3.y);
            fma2(accB[2 * q],     pB0, w0.x); fma2(accB[2 * q + 1], pB0, w0.y);
            fma2(accB[2 * q],     pB1, w1.x); fma2(accB[2 * q + 1], pB1, w1.y);
            fma2(accB[2 * q],     pB2, w2.x); fma2(accB[2 * q + 1], pB2, w2.y);
            fma2(accB[2 * q],     pB3, w3.x); fma2(accB[2 * q + 1], pB3, w3.y);
        }
    }

    // ---- epilogue: swish + STS.128 stage + LDS.64/STG.64 transpose ----
    float* srow = sOutBase + (warp * 32 + lane) * 36;   // stride 36 -> conflict-free STS.128
    const int o2   = (lane & 15) * 2;
    const int joff = lane >> 4;
#pragma unroll
    for (int s = 0; s < 2; s++) {
        u64* acc = s ? accB : accA;
        float* obase = out + ((size_t)i * N_NODES + j0 + (s ? 32 : 0)) * OUTF;

#pragma unroll
        for (int p = 0; p < 8; p++) {
            u64 h0 = mul2r(acc[2 * p],     halfp);
            u64 h1 = mul2r(acc[2 * p + 1], halfp);
            float v0, v1, v2, v3;
            unpack2(h0, v0, v1);
            unpack2(h1, v2, v3);
            float4 v = make_float4(swish_from_half(v0), swish_from_half(v1),
                                   swish_from_half(v2), swish_from_half(v3));
            ((float4*)srow)[p] = v;
        }
        __syncwarp();

        const float* swarp = sOutBase + warp * 32 * 36;
#pragma unroll
        for (int r = 0; r < 16; r++) {
            int jj = 2 * r + joff;
            float2 v = *(const float2*)(swarp + jj * 36 + o2);
            __stcs((float2*)(obase + jj * OUTF + o2), v);
        }
        __syncwarp();
    }
}

// ---------------------------------------------------------------------------
extern "C" void kernel_launch(void* const* d_in, const int* in_sizes, int n_in,
                              void* d_out, int out_size) {
    const float* Edges  = (const float*)d_in[0];
    const float* Coords = (const float*)d_in[1];
    const float* Emb    = (const float*)d_in[2];
    const float* W1     = (const float*)d_in[3];
    const float* b1     = (const float*)d_in[4];
    const float* W2     = (const float*)d_in[5];
    const float* b2     = (const float*)d_in[6];
    float* out = (float*)d_out;

    static bool attr_set = false;
    if (!attr_set) {
        cudaFuncSetAttribute(phi_e_kernel,
                             cudaFuncAttributeMaxDynamicSharedMemorySize,
                             SMEM_TOTAL);
        attr_set = true;
    }

    cudaMemcpyToSymbolAsync(c_b2, b2, OUTF * sizeof(float), 0,
                            cudaMemcpyDeviceToDevice);

    prep_kernel<<<128, 256>>>(Emb, W1, W2);   // also writes g_W2T (block 0)

    void* w2t_dev = nullptr;
    cudaGetSymbolAddress(&w2t_dev, g_W2T);
    cudaMemcpyToSymbolAsync(c_W2T, w2t_dev, HID * OUTF * sizeof(float), 0,
                            cudaMemcpyDeviceToDevice);

    dim3 grid(N_NODES / 64, N_NODES / 8);
    phi_e_kernel<<<grid, 256, SMEM_TOTAL>>>(Edges, Coords, b1, out);
}